// round 16
// baseline (speedup 1.0000x reference)
#include <cuda_runtime.h>
#include <cstddef>
#include <cstdint>

// Problem constants
#define BB 32
#define SS 1024
#define EE 512
#define HH 1024
#define GG 4096          // 4*H
#define DKV 512

#define NBLK 128         // persistent grid: 1 block/SM
#define NTHR 256

#define RSTRIDE 34       // k-reduce row stride (even -> float2 8B-aligned)
#define HSTRIDE 40       // hT slab row stride: bank = (8k+b)&31 conflict-free

#define SA 36            // gemm smem row stride (u32): bank-uniform

// Scratch (device globals; no allocation allowed)
// g_xg layout: [S][B][4H]   (step-major; written by phase A with perm=1)
// g_hs layout: [S][B][H]    (step-major, tf32-rounded bits; phase C input)
__device__ __align__(16) float g_xg[(size_t)BB * SS * GG];
__device__ __align__(16) float g_hs[(size_t)BB * SS * HH];
__device__ __align__(16) float g_hT[2][HH * BB];             // ping-pong h^T [k][b], tf32-rounded
__device__ unsigned int g_doneg[SS * 4];                     // per-step per-group (32 blocks) counters
__device__ unsigned int g_arrive = 0;
__device__ unsigned int g_gen = 0;

// pre-converted tf32 gemm inputs
__device__ __align__(16) uint32_t g_xt[(size_t)BB * SS * EE];   // x  (tf32 bits)
__device__ __align__(16) uint32_t g_wih[(size_t)GG * EE];       // W_ih
__device__ __align__(16) uint32_t g_wkey[(size_t)DKV * HH];     // W_key
__device__ __align__(16) uint32_t g_wval[(size_t)DKV * HH];     // W_val

// ---------------------------------------------------------------------------
// helpers
// ---------------------------------------------------------------------------
__device__ __forceinline__ uint32_t f2tf32(float f) {
    uint32_t u;
    asm("cvt.rna.tf32.f32 %0, %1;" : "=r"(u) : "f"(f));
    return u;
}

__device__ __forceinline__ void mma_tf32(float& d0, float& d1, float& d2, float& d3,
                                         uint32_t a0, uint32_t a1, uint32_t a2, uint32_t a3,
                                         uint32_t b0, uint32_t b1) {
    asm("mma.sync.aligned.m16n8k8.row.col.f32.tf32.tf32.f32 "
        "{%0,%1,%2,%3}, {%4,%5,%6,%7}, {%8,%9}, {%0,%1,%2,%3};"
        : "+f"(d0), "+f"(d1), "+f"(d2), "+f"(d3)
        : "r"(a0), "r"(a1), "r"(a2), "r"(a3), "r"(b0), "r"(b1));
}

__device__ __forceinline__ void cpa16(void* smem, const void* g) {
    uint32_t s = (uint32_t)__cvta_generic_to_shared(smem);
    asm volatile("cp.async.cg.shared.global [%0], [%1], 16;" :: "r"(s), "l"(g));
}
__device__ __forceinline__ void cpa_commit() {
    asm volatile("cp.async.commit_group;");
}
__device__ __forceinline__ void cpa_wait1() {
    asm volatile("cp.async.wait_group 1;");
}
__device__ __forceinline__ void cpa_wait0() {
    asm volatile("cp.async.wait_group 0;");
}

// ---------------------------------------------------------------------------
// elementwise fp32 -> tf32-bits pre-conversion
// ---------------------------------------------------------------------------
__global__ void cvt_tf32_kernel(const float* __restrict__ src,
                                uint32_t* __restrict__ dst, int n4) {
    int i = blockIdx.x * blockDim.x + threadIdx.x;
    if (i < n4) {
        float4 v = *(const float4*)&src[i * 4];
        uint4 t;
        t.x = f2tf32(v.x); t.y = f2tf32(v.y);
        t.z = f2tf32(v.z); t.w = f2tf32(v.w);
        *(uint4*)&dst[i * 4] = t;
    }
}

// ---------------------------------------------------------------------------
// tf32 tensor-core GEMM v3 (unchanged, passing): pre-converted inputs,
// cp.async staging into bank-uniform smem, 1 sync/kt.
// perm: 0 = identity; 1 = xg perm; 2 = out perm
// ---------------------------------------------------------------------------
__global__ void __launch_bounds__(256, 2)
gemm_tf32(const uint32_t* __restrict__ A,
          const uint32_t* __restrict__ W,
          const float* __restrict__ bias1,
          const float* __restrict__ bias2,
          float* __restrict__ C,
          int M, int N, int K, int perm) {
    extern __shared__ uint32_t gsm[];   // 2 stages x (As 128*SA + Bs 128*SA)

    const int tid  = threadIdx.x;
    const int lane = tid & 31;
    const int wid  = tid >> 5;
    const int mw   = wid >> 1;
    const int nw   = wid & 1;
    const int row0 = blockIdx.y * 128;
    const int col0 = blockIdx.x * 128;

    const int STAGE = 2 * 128 * SA;

#define ISSUE_GT(kt)                                                          \
    do {                                                                      \
        uint32_t* As = gsm + ((kt) & 1) * STAGE;                              \
        uint32_t* Bs = As + 128 * SA;                                         \
        _Pragma("unroll")                                                     \
        for (int i = 0; i < 4; i++) {                                         \
            int v = tid + i * 256, row = v >> 3, kq = v & 7;                  \
            cpa16(&As[row * SA + kq * 4],                                     \
                  &A[(size_t)(row0 + row) * K + (kt) * 32 + kq * 4]);         \
        }                                                                     \
        _Pragma("unroll")                                                     \
        for (int i = 0; i < 4; i++) {                                         \
            int v = tid + i * 256, n = v >> 3, kq = v & 7;                    \
            cpa16(&Bs[n * SA + kq * 4],                                       \
                  &W[(size_t)(col0 + n) * K + (kt) * 32 + kq * 4]);           \
        }                                                                     \
        cpa_commit();                                                         \
    } while (0)

    float acc[2][8][4];
#pragma unroll
    for (int i = 0; i < 2; i++)
#pragma unroll
        for (int j = 0; j < 8; j++)
#pragma unroll
            for (int r = 0; r < 4; r++) acc[i][j][r] = 0.f;

    const int niter = K / 32;
    ISSUE_GT(0);

    const int lm = lane >> 2;
    const int lk = lane & 3;

    for (int kt = 0; kt < niter; kt++) {
        cpa_wait0();
        __syncthreads();
        if (kt + 1 < niter) ISSUE_GT(kt + 1);

        const uint32_t* st = gsm + (kt & 1) * STAGE;
        const uint32_t* Abase = st + (mw * 32 + lm) * SA + lk;
        const uint32_t* Bbase = st + 128 * SA + (nw * 64 + lm) * SA + lk;

#pragma unroll
        for (int ks = 0; ks < 4; ks++) {
            uint32_t av[2][4];
#pragma unroll
            for (int i = 0; i < 2; i++) {
                const uint32_t* p = Abase + i * 16 * SA + ks * 8;
                av[i][0] = p[0];
                av[i][1] = p[8 * SA];
                av[i][2] = p[4];
                av[i][3] = p[8 * SA + 4];
            }
#pragma unroll
            for (int j = 0; j < 8; j++) {
                const uint32_t* q = Bbase + j * 8 * SA + ks * 8;
                uint32_t b0 = q[0];
                uint32_t b1 = q[4];
#pragma unroll
                for (int i = 0; i < 2; i++)
                    mma_tf32(acc[i][j][0], acc[i][j][1], acc[i][j][2], acc[i][j][3],
                             av[i][0], av[i][1], av[i][2], av[i][3], b0, b1);
            }
        }
    }

#pragma unroll
    for (int i = 0; i < 2; i++) {
#pragma unroll
        for (int j = 0; j < 8; j++) {
            int row = row0 + mw * 32 + i * 16 + (lane >> 2);
            int col = col0 + nw * 64 + j * 8 + (lane & 3) * 2;
            float bb0 = 0.f, bb1 = 0.f;
            if (bias1) { bb0 += bias1[col]; bb1 += bias1[col + 1]; }
            if (bias2) { bb0 += bias2[col]; bb1 += bias2[col + 1]; }
            int r0 = row, r1 = row + 8;
            if (perm == 1) {
                r0 = (r0 & (SS - 1)) * BB + (r0 >> 10);
                r1 = (r1 & (SS - 1)) * BB + (r1 >> 10);
            } else if (perm == 2) {
                r0 = (r0 & 31) * SS + (r0 >> 5);
                r1 = (r1 & 31) * SS + (r1 >> 5);
            }
            *(float2*)&C[(size_t)r0 * N + col] =
                make_float2(acc[i][j][0] + bb0, acc[i][j][1] + bb1);
            *(float2*)&C[(size_t)r1 * N + col] =
                make_float2(acc[i][j][2] + bb0, acc[i][j][3] + bb1);
        }
    }
#undef ISSUE_GT
}

// ---------------------------------------------------------------------------
// Atomic grid barrier (startup only; graph-replay safe).
// ---------------------------------------------------------------------------
__device__ __forceinline__ void grid_barrier() {
    __syncthreads();
    if (threadIdx.x == 0) {
        unsigned int gen = *((volatile unsigned int*)&g_gen);
        __threadfence();
        if (atomicAdd(&g_arrive, 1u) == NBLK - 1) {
            g_arrive = 0;
            __threadfence();
            atomicAdd(&g_gen, 1u);
        } else {
            while (*((volatile unsigned int*)&g_gen) == gen) { }
        }
    }
    __syncthreads();
}

// ---------------------------------------------------------------------------
// Persistent tf32-MMA LSTM recurrence, v8: group-granular chunk gating.
// Chunk c's k-rows are produced by block group c (blocks 32c..32c+31).
// Publishers RED into g_doneg[t*4 + group]. Each warp gates ISSUE_CHUNK(c)
// on group c only (lane-0 nanosleep poll, expected-ready, brief), so a
// straggler in group g delays only chunks >= g and release is per-warp.
// WAR safety identical to v5: a block writes buffer t&1 at step t+1 only
// after consuming all 4 groups of step t (all 128 blocks' reads done).
// 2 block syncs/step (post-reduce, pre-publish).
// ---------------------------------------------------------------------------
extern __shared__ float smem_dyn[];

__global__ void __launch_bounds__(NTHR, 1)
lstm_persistent(const float* __restrict__ W_hh) {
    uint32_t* Wf = (uint32_t*)smem_dyn;        // 32768 u32 (128 KB)
    float* slabs = smem_dyn + 32768;           // [2 buf][8 warp][32 row][HSTRIDE]

    const int tid  = threadIdx.x;
    const int lane = tid & 31;
    const int wid  = tid >> 5;
    const int blk  = blockIdx.x;
    const int hb   = blk * 8;

    float* redw = slabs + (wid * 32) * HSTRIDE;

    for (int idx = tid; idx < 32768; idx += NTHR) {
        int r  = idx & 3;
        int L  = (idx >> 2) & 31;
        int ks = (idx >> 7) & 127;
        int mt = idx >> 14;
        int c  = mt * 16 + (L >> 2) + (r & 1) * 8;
        int k  = ks * 8 + (L & 3) + (r >> 1) * 4;
        int g  = c >> 3, hh = c & 7;
        Wf[idx] = f2tf32(W_hh[(size_t)(g * HH + hb + hh) * HH + k]);
    }

    for (int i = blk * NTHR + tid; i < SS * 4; i += NBLK * NTHR)
        g_doneg[i] = 0u;
    for (int i = blk * NTHR + tid; i < HH * BB; i += NBLK * NTHR)
        g_hT[0][i] = 0.f;
    grid_barrier();

    const int b_e  = tid >> 3;
    const int hh_e = tid & 7;
    float cstate = 0.f;

    for (int t = 0; t < SS; t++) {
        const float* __restrict__ hsrc = g_hT[t & 1];

        // xg prefetch (independent of hT; before any gate)
        float xp[4];
        {
            size_t base = ((size_t)t * BB + b_e) * GG + hb + hh_e;
#pragma unroll
            for (int g = 0; g < 4; g++)
                xp[g] = __ldcg(&g_xg[base + (size_t)g * HH]);
        }

        float acc[2][4][4];
#pragma unroll
        for (int m = 0; m < 2; m++)
#pragma unroll
            for (int n = 0; n < 4; n++)
#pragma unroll
                for (int r = 0; r < 4; r++) acc[m][n][r] = 0.f;

        // per-warp gate: chunk g's producers (blocks 32g..32g+31) done step t-1
#define GATE(gi)                                                              \
        do {                                                                  \
            if (t > 0) {                                                      \
                if (lane == 0) {                                              \
                    while (*((volatile unsigned int*)                         \
                             &g_doneg[(t - 1) * 4 + (gi)]) < 32u)             \
                        __nanosleep(32);                                      \
                }                                                             \
                __syncwarp();                                                 \
            }                                                                 \
        } while (0)

#define ISSUE_CHUNK(c)                                                        \
        do {                                                                  \
            float* dst = slabs + ((((c) & 1) * 8 + wid) * 32) * HSTRIDE;      \
            const int base_row = ((c) * 32 + wid * 4) * 8;                    \
            _Pragma("unroll")                                                 \
            for (int q = 0; q < 8; q++) {                                     \
                int s = lane + 32 * q;                                        \
                int lr = s >> 3, c4 = s & 7;                                  \
                cpa16(dst + lr * HSTRIDE + c4 * 4,                            \
                      &hsrc[(base_row + lr) * BB + c4 * 4]);                  \
            }                                                                 \
            cpa_commit();                                                     \
        } while (0)

        GATE(0);
        ISSUE_CHUNK(0);
        GATE(1);
        ISSUE_CHUNK(1);

#pragma unroll
        for (int c = 0; c < 4; c++) {
            if (c < 3) cpa_wait1(); else cpa_wait0();
            __syncwarp();
            const float* sl = slabs + (((c & 1) * 8 + wid) * 32) * HSTRIDE;
#pragma unroll
            for (int j = 0; j < 4; j++) {
                const int ksg = c * 32 + wid * 4 + j;
                uint4 A0 = *(const uint4*)&Wf[(0 * 128 + ksg) * 128 + lane * 4];
                uint4 A1 = *(const uint4*)&Wf[(1 * 128 + ksg) * 128 + lane * 4];
                const float* bp0 = &sl[(j * 8 + (lane & 3)) * HSTRIDE + (lane >> 2)];
                const float* bp1 = bp0 + 4 * HSTRIDE;
#pragma unroll
                for (int ng = 0; ng < 4; ng++) {
                    uint32_t b0 = __float_as_uint(bp0[ng * 8]);
                    uint32_t b1 = __float_as_uint(bp1[ng * 8]);
                    mma_tf32(acc[0][ng][0], acc[0][ng][1], acc[0][ng][2], acc[0][ng][3],
                             A0.x, A0.y, A0.z, A0.w, b0, b1);
                    mma_tf32(acc[1][ng][0], acc[1][ng][1], acc[1][ng][2], acc[1][ng][3],
                             A1.x, A1.y, A1.z, A1.w, b0, b1);
                }
            }
            if (c < 2) {
                GATE(c + 2);
                ISSUE_CHUNK(c + 2);
            }
        }
#undef ISSUE_CHUNK
#undef GATE

        // k-reduce into warp-private region (own buf0 slab)
#pragma unroll
        for (int mt = 0; mt < 2; mt++) {
#pragma unroll
            for (int ng = 0; ng < 4; ng++) {
                int c0 = mt * 16 + (lane >> 2);
                int b0 = ng * 8 + 2 * (lane & 3);
                *(float2*)&redw[(c0)     * RSTRIDE + b0] =
                    make_float2(acc[mt][ng][0], acc[mt][ng][1]);
                *(float2*)&redw[(c0 + 8) * RSTRIDE + b0] =
                    make_float2(acc[mt][ng][2], acc[mt][ng][3]);
            }
        }
        __syncthreads();   // all warps' red regions visible

        // elementwise update (one cell per thread; cell state in regs)
        {
            float gate[4];
#pragma unroll
            for (int g = 0; g < 4; g++) {
                float s = xp[g];
#pragma unroll
                for (int w = 0; w < 8; w++)
                    s += slabs[(w * 32) * HSTRIDE + (g * 8 + hh_e) * RSTRIDE + b_e];
                gate[g] = s;
            }
            float iv = 1.f / (1.f + __expf(-gate[0]));
            float fv = 1.f / (1.f + __expf(-gate[1]));
            float gv = tanhf(gate[2]);
            float ov = 1.f / (1.f + __expf(-gate[3]));
            cstate = fv * cstate + iv * gv;
            float hv = ov * tanhf(cstate);
            uint32_t hvt = f2tf32(hv);
            g_hT[(t + 1) & 1][(hb + hh_e) * BB + b_e] = __uint_as_float(hvt);
            g_hs[((size_t)t * BB + b_e) * HH + hb + hh_e] = __uint_as_float(hvt);
        }

        __syncthreads();   // hT slice fully written; red fully read
        if (tid == 0) {
            __threadfence();
            atomicAdd(&g_doneg[t * 4 + (blk >> 5)], 1u);
        }
    }
}

// ---------------------------------------------------------------------------
// Launch
// ---------------------------------------------------------------------------
extern "C" void kernel_launch(void* const* d_in, const int* in_sizes, int n_in,
                              void* d_out, int out_size) {
    const float* x     = (const float*)d_in[0];
    const float* W_ih  = (const float*)d_in[1];
    const float* W_hh  = (const float*)d_in[2];
    const float* b_ih  = (const float*)d_in[3];
    const float* b_hh  = (const float*)d_in[4];
    const float* W_key = (const float*)d_in[5];
    const float* b_key = (const float*)d_in[6];
    const float* W_val = (const float*)d_in[7];
    const float* b_val = (const float*)d_in[8];
    float* out = (float*)d_out;

    float* xg_ptr = nullptr;
    float* hs_ptr = nullptr;
    uint32_t *xt_ptr = nullptr, *wih_ptr = nullptr, *wkey_ptr = nullptr, *wval_ptr = nullptr;
    cudaGetSymbolAddress((void**)&xg_ptr, g_xg);
    cudaGetSymbolAddress((void**)&hs_ptr, g_hs);
    cudaGetSymbolAddress((void**)&xt_ptr, g_xt);
    cudaGetSymbolAddress((void**)&wih_ptr, g_wih);
    cudaGetSymbolAddress((void**)&wkey_ptr, g_wkey);
    cudaGetSymbolAddress((void**)&wval_ptr, g_wval);

    const int M = BB * SS;   // 32768
    const int LSTM_SMEM = (32768 + 2 * 8 * 32 * HSTRIDE) * 4;   // 212,992 B
    const int GEMM_SMEM = 2 * 2 * 128 * SA * 4;                 //  73,728 B

    cudaFuncSetAttribute(lstm_persistent,
                         cudaFuncAttributeMaxDynamicSharedMemorySize, LSTM_SMEM);
    cudaFuncSetAttribute(gemm_tf32,
                         cudaFuncAttributeMaxDynamicSharedMemorySize, GEMM_SMEM);

    // Pre-convert gemm inputs to tf32 bits (bit-identical to in-loop cvt)
    {
        int n;
        n = BB * SS * EE / 4;
        cvt_tf32_kernel<<<(n + 255) / 256, 256>>>(x, xt_ptr, n);
        n = GG * EE / 4;
        cvt_tf32_kernel<<<(n + 255) / 256, 256>>>(W_ih, wih_ptr, n);
        n = DKV * HH / 4;
        cvt_tf32_kernel<<<(n + 255) / 256, 256>>>(W_key, wkey_ptr, n);
        cvt_tf32_kernel<<<(n + 255) / 256, 256>>>(W_val, wval_ptr, n);
    }

    // Phase A: xg[S][B][4H] = perm1( x @ W_ih^T + b_ih + b_hh )
    {
        dim3 grid(GG / 128, M / 128);
        gemm_tf32<<<grid, 256, GEMM_SMEM>>>(xt_ptr, wih_ptr, b_ih, b_hh, xg_ptr, M, GG, EE, 1);
    }

    // Phase B: persistent tf32-MMA LSTM recurrence (single launch)
    lstm_persistent<<<NBLK, NTHR, LSTM_SMEM>>>(W_hh);

    // Phase C: keys / values; hs holds tf32 bits -> out rows permuted (perm=2)
    {
        dim3 grid(DKV / 128, M / 128);
        gemm_tf32<<<grid, 256, GEMM_SMEM>>>((const uint32_t*)hs_ptr, wkey_ptr, b_key, nullptr,
                                            out, M, DKV, HH, 2);
        gemm_tf32<<<grid, 256, GEMM_SMEM>>>((const uint32_t*)hs_ptr, wval_ptr, b_val, nullptr,
                                            out + (size_t)M * DKV, M, DKV, HH, 2);
    }
}

// round 17
// speedup vs baseline: 1.1905x; 1.1905x over previous
#include <cuda_runtime.h>
#include <cstddef>
#include <cstdint>

// Problem constants
#define BB 32
#define SS 1024
#define EE 512
#define HH 1024
#define GG 4096          // 4*H
#define DKV 512

#define NBLK 128         // persistent grid: 1 block/SM
#define NTHR 256

#define RSTRIDE 34       // k-reduce row stride (even -> float2 8B-aligned)
#define HSTRIDE 40       // hT slab row stride: bank = (8k+b)&31 conflict-free

#define SA 36            // gemm smem row stride (u32): bank-uniform

// Scratch (device globals; no allocation allowed)
// g_xg layout: [S][B][4H]   (step-major; written by phase A with perm=1)
// g_hs layout: [S][B][H]    (step-major, tf32-rounded bits; phase C input)
__device__ __align__(16) float g_xg[(size_t)BB * SS * GG];
__device__ __align__(16) float g_hs[(size_t)BB * SS * HH];
__device__ __align__(16) float g_hT[2][HH * BB];             // ping-pong h^T [k][b], tf32-rounded
__device__ unsigned int g_done[SS];                          // per-step completion counters
__device__ unsigned int g_arrive = 0;
__device__ unsigned int g_gen = 0;

// pre-converted tf32 gemm inputs
__device__ __align__(16) uint32_t g_xt[(size_t)BB * SS * EE];   // x  (tf32 bits)
__device__ __align__(16) uint32_t g_wih[(size_t)GG * EE];       // W_ih
__device__ __align__(16) uint32_t g_wkey[(size_t)DKV * HH];     // W_key
__device__ __align__(16) uint32_t g_wval[(size_t)DKV * HH];     // W_val

// ---------------------------------------------------------------------------
// helpers
// ---------------------------------------------------------------------------
__device__ __forceinline__ uint32_t f2tf32(float f) {
    uint32_t u;
    asm("cvt.rna.tf32.f32 %0, %1;" : "=r"(u) : "f"(f));
    return u;
}

__device__ __forceinline__ void mma_tf32(float& d0, float& d1, float& d2, float& d3,
                                         uint32_t a0, uint32_t a1, uint32_t a2, uint32_t a3,
                                         uint32_t b0, uint32_t b1) {
    asm("mma.sync.aligned.m16n8k8.row.col.f32.tf32.tf32.f32 "
        "{%0,%1,%2,%3}, {%4,%5,%6,%7}, {%8,%9}, {%0,%1,%2,%3};"
        : "+f"(d0), "+f"(d1), "+f"(d2), "+f"(d3)
        : "r"(a0), "r"(a1), "r"(a2), "r"(a3), "r"(b0), "r"(b1));
}

__device__ __forceinline__ void cpa16(void* smem, const void* g) {
    uint32_t s = (uint32_t)__cvta_generic_to_shared(smem);
    asm volatile("cp.async.cg.shared.global [%0], [%1], 16;" :: "r"(s), "l"(g));
}
__device__ __forceinline__ void cpa_commit() {
    asm volatile("cp.async.commit_group;");
}
__device__ __forceinline__ void cpa_wait1() {
    asm volatile("cp.async.wait_group 1;");
}
__device__ __forceinline__ void cpa_wait0() {
    asm volatile("cp.async.wait_group 0;");
}

// ---------------------------------------------------------------------------
// elementwise fp32 -> tf32-bits pre-conversion
// ---------------------------------------------------------------------------
__global__ void cvt_tf32_kernel(const float* __restrict__ src,
                                uint32_t* __restrict__ dst, int n4) {
    int i = blockIdx.x * blockDim.x + threadIdx.x;
    if (i < n4) {
        float4 v = *(const float4*)&src[i * 4];
        uint4 t;
        t.x = f2tf32(v.x); t.y = f2tf32(v.y);
        t.z = f2tf32(v.z); t.w = f2tf32(v.w);
        *(uint4*)&dst[i * 4] = t;
    }
}

// ---------------------------------------------------------------------------
// tf32 tensor-core GEMM v4: pre-converted inputs, cp.async staging into
// bank-uniform smem, THREE-stage pipeline (copy gets 2 mma iters to land).
// perm: 0 = identity; 1 = xg perm; 2 = out perm
// ---------------------------------------------------------------------------
__global__ void __launch_bounds__(256, 2)
gemm_tf32(const uint32_t* __restrict__ A,
          const uint32_t* __restrict__ W,
          const float* __restrict__ bias1,
          const float* __restrict__ bias2,
          float* __restrict__ C,
          int M, int N, int K, int perm) {
    extern __shared__ uint32_t gsm[];   // 3 stages x (As 128*SA + Bs 128*SA)

    const int tid  = threadIdx.x;
    const int lane = tid & 31;
    const int wid  = tid >> 5;
    const int mw   = wid >> 1;
    const int nw   = wid & 1;
    const int row0 = blockIdx.y * 128;
    const int col0 = blockIdx.x * 128;

    const int STAGE = 2 * 128 * SA;

#define ISSUE_GT(kt)                                                          \
    do {                                                                      \
        uint32_t* As = gsm + ((kt) % 3) * STAGE;                              \
        uint32_t* Bs = As + 128 * SA;                                         \
        _Pragma("unroll")                                                     \
        for (int i = 0; i < 4; i++) {                                         \
            int v = tid + i * 256, row = v >> 3, kq = v & 7;                  \
            cpa16(&As[row * SA + kq * 4],                                     \
                  &A[(size_t)(row0 + row) * K + (kt) * 32 + kq * 4]);         \
        }                                                                     \
        _Pragma("unroll")                                                     \
        for (int i = 0; i < 4; i++) {                                         \
            int v = tid + i * 256, n = v >> 3, kq = v & 7;                    \
            cpa16(&Bs[n * SA + kq * 4],                                       \
                  &W[(size_t)(col0 + n) * K + (kt) * 32 + kq * 4]);           \
        }                                                                     \
        cpa_commit();                                                         \
    } while (0)

    float acc[2][8][4];
#pragma unroll
    for (int i = 0; i < 2; i++)
#pragma unroll
        for (int j = 0; j < 8; j++)
#pragma unroll
            for (int r = 0; r < 4; r++) acc[i][j][r] = 0.f;

    const int niter = K / 32;
    ISSUE_GT(0);
    ISSUE_GT(1);

    const int lm = lane >> 2;
    const int lk = lane & 3;

    for (int kt = 0; kt < niter; kt++) {
        // >=2 groups pending except at the tail; wait1 completes stage kt.
        if (kt + 1 < niter) cpa_wait1(); else cpa_wait0();
        __syncthreads();      // stage kt visible; stage (kt+2)%3 free (mma kt-1 done)
        if (kt + 2 < niter) ISSUE_GT(kt + 2);   // overlaps mma kt (and kt+1)

        const uint32_t* st = gsm + (kt % 3) * STAGE;
        const uint32_t* Abase = st + (mw * 32 + lm) * SA + lk;
        const uint32_t* Bbase = st + 128 * SA + (nw * 64 + lm) * SA + lk;

#pragma unroll
        for (int ks = 0; ks < 4; ks++) {
            uint32_t av[2][4];
#pragma unroll
            for (int i = 0; i < 2; i++) {
                const uint32_t* p = Abase + i * 16 * SA + ks * 8;
                av[i][0] = p[0];
                av[i][1] = p[8 * SA];
                av[i][2] = p[4];
                av[i][3] = p[8 * SA + 4];
            }
#pragma unroll
            for (int j = 0; j < 8; j++) {
                const uint32_t* q = Bbase + j * 8 * SA + ks * 8;
                uint32_t b0 = q[0];
                uint32_t b1 = q[4];
#pragma unroll
                for (int i = 0; i < 2; i++)
                    mma_tf32(acc[i][j][0], acc[i][j][1], acc[i][j][2], acc[i][j][3],
                             av[i][0], av[i][1], av[i][2], av[i][3], b0, b1);
            }
        }
    }

#pragma unroll
    for (int i = 0; i < 2; i++) {
#pragma unroll
        for (int j = 0; j < 8; j++) {
            int row = row0 + mw * 32 + i * 16 + (lane >> 2);
            int col = col0 + nw * 64 + j * 8 + (lane & 3) * 2;
            float bb0 = 0.f, bb1 = 0.f;
            if (bias1) { bb0 += bias1[col]; bb1 += bias1[col + 1]; }
            if (bias2) { bb0 += bias2[col]; bb1 += bias2[col + 1]; }
            int r0 = row, r1 = row + 8;
            if (perm == 1) {
                r0 = (r0 & (SS - 1)) * BB + (r0 >> 10);
                r1 = (r1 & (SS - 1)) * BB + (r1 >> 10);
            } else if (perm == 2) {
                r0 = (r0 & 31) * SS + (r0 >> 5);
                r1 = (r1 & 31) * SS + (r1 >> 5);
            }
            *(float2*)&C[(size_t)r0 * N + col] =
                make_float2(acc[i][j][0] + bb0, acc[i][j][1] + bb1);
            *(float2*)&C[(size_t)r1 * N + col] =
                make_float2(acc[i][j][2] + bb0, acc[i][j][3] + bb1);
        }
    }
#undef ISSUE_GT
}

// ---------------------------------------------------------------------------
// Atomic grid barrier (startup only; graph-replay safe).
// ---------------------------------------------------------------------------
__device__ __forceinline__ void grid_barrier() {
    __syncthreads();
    if (threadIdx.x == 0) {
        unsigned int gen = *((volatile unsigned int*)&g_gen);
        __threadfence();
        if (atomicAdd(&g_arrive, 1u) == NBLK - 1) {
            g_arrive = 0;
            __threadfence();
            atomicAdd(&g_gen, 1u);
        } else {
            while (*((volatile unsigned int*)&g_gen) == gen) { }
        }
    }
    __syncthreads();
}

// ---------------------------------------------------------------------------
// Persistent tf32-MMA LSTM recurrence (v5 — locked best config).
// ---------------------------------------------------------------------------
extern __shared__ float smem_dyn[];

__global__ void __launch_bounds__(NTHR, 1)
lstm_persistent(const float* __restrict__ W_hh) {
    uint32_t* Wf = (uint32_t*)smem_dyn;        // 32768 u32 (128 KB)
    float* slabs = smem_dyn + 32768;           // [2 buf][8 warp][32 row][HSTRIDE]

    const int tid  = threadIdx.x;
    const int lane = tid & 31;
    const int wid  = tid >> 5;
    const int blk  = blockIdx.x;
    const int hb   = blk * 8;

    float* redw = slabs + (wid * 32) * HSTRIDE;

    for (int idx = tid; idx < 32768; idx += NTHR) {
        int r  = idx & 3;
        int L  = (idx >> 2) & 31;
        int ks = (idx >> 7) & 127;
        int mt = idx >> 14;
        int c  = mt * 16 + (L >> 2) + (r & 1) * 8;
        int k  = ks * 8 + (L & 3) + (r >> 1) * 4;
        int g  = c >> 3, hh = c & 7;
        Wf[idx] = f2tf32(W_hh[(size_t)(g * HH + hb + hh) * HH + k]);
    }

    for (int i = blk * NTHR + tid; i < SS; i += NBLK * NTHR)
        g_done[i] = 0u;
    for (int i = blk * NTHR + tid; i < HH * BB; i += NBLK * NTHR)
        g_hT[0][i] = 0.f;
    grid_barrier();

    const int b_e  = tid >> 3;
    const int hh_e = tid & 7;
    float cstate = 0.f;

    for (int t = 0; t < SS; t++) {
        const float* __restrict__ hsrc = g_hT[t & 1];

        float xp[4];
        {
            size_t base = ((size_t)t * BB + b_e) * GG + hb + hh_e;
#pragma unroll
            for (int g = 0; g < 4; g++)
                xp[g] = __ldcg(&g_xg[base + (size_t)g * HH]);
        }

        if (t > 0) {
            if (tid == 0) {
                while (*((volatile unsigned int*)&g_done[t - 1]) < NBLK)
                    __nanosleep(32);
            }
            __syncthreads();
        }

        float acc[2][4][4];
#pragma unroll
        for (int m = 0; m < 2; m++)
#pragma unroll
            for (int n = 0; n < 4; n++)
#pragma unroll
                for (int r = 0; r < 4; r++) acc[m][n][r] = 0.f;

#define ISSUE_CHUNK(c)                                                        \
        do {                                                                  \
            float* dst = slabs + ((((c) & 1) * 8 + wid) * 32) * HSTRIDE;      \
            const int base_row = ((c) * 32 + wid * 4) * 8;                    \
            _Pragma("unroll")                                                 \
            for (int q = 0; q < 8; q++) {                                     \
                int s = lane + 32 * q;                                        \
                int lr = s >> 3, c4 = s & 7;                                  \
                cpa16(dst + lr * HSTRIDE + c4 * 4,                            \
                      &hsrc[(base_row + lr) * BB + c4 * 4]);                  \
            }                                                                 \
            cpa_commit();                                                     \
        } while (0)

        ISSUE_CHUNK(0);
        ISSUE_CHUNK(1);

#pragma unroll
        for (int c = 0; c < 4; c++) {
            if (c < 3) cpa_wait1(); else cpa_wait0();
            __syncwarp();
            const float* sl = slabs + (((c & 1) * 8 + wid) * 32) * HSTRIDE;
#pragma unroll
            for (int j = 0; j < 4; j++) {
                const int ksg = c * 32 + wid * 4 + j;
                uint4 A0 = *(const uint4*)&Wf[(0 * 128 + ksg) * 128 + lane * 4];
                uint4 A1 = *(const uint4*)&Wf[(1 * 128 + ksg) * 128 + lane * 4];
                const float* bp0 = &sl[(j * 8 + (lane & 3)) * HSTRIDE + (lane >> 2)];
                const float* bp1 = bp0 + 4 * HSTRIDE;
#pragma unroll
                for (int ng = 0; ng < 4; ng++) {
                    uint32_t b0 = __float_as_uint(bp0[ng * 8]);
                    uint32_t b1 = __float_as_uint(bp1[ng * 8]);
                    mma_tf32(acc[0][ng][0], acc[0][ng][1], acc[0][ng][2], acc[0][ng][3],
                             A0.x, A0.y, A0.z, A0.w, b0, b1);
                    mma_tf32(acc[1][ng][0], acc[1][ng][1], acc[1][ng][2], acc[1][ng][3],
                             A1.x, A1.y, A1.z, A1.w, b0, b1);
                }
            }
            if (c < 2) ISSUE_CHUNK(c + 2);
        }
#undef ISSUE_CHUNK

#pragma unroll
        for (int mt = 0; mt < 2; mt++) {
#pragma unroll
            for (int ng = 0; ng < 4; ng++) {
                int c0 = mt * 16 + (lane >> 2);
                int b0 = ng * 8 + 2 * (lane & 3);
                *(float2*)&redw[(c0)     * RSTRIDE + b0] =
                    make_float2(acc[mt][ng][0], acc[mt][ng][1]);
                *(float2*)&redw[(c0 + 8) * RSTRIDE + b0] =
                    make_float2(acc[mt][ng][2], acc[mt][ng][3]);
            }
        }
        __syncthreads();

        {
            float gate[4];
#pragma unroll
            for (int g = 0; g < 4; g++) {
                float s = xp[g];
#pragma unroll
                for (int w = 0; w < 8; w++)
                    s += slabs[(w * 32) * HSTRIDE + (g * 8 + hh_e) * RSTRIDE + b_e];
                gate[g] = s;
            }
            float iv = 1.f / (1.f + __expf(-gate[0]));
            float fv = 1.f / (1.f + __expf(-gate[1]));
            float gv = tanhf(gate[2]);
            float ov = 1.f / (1.f + __expf(-gate[3]));
            cstate = fv * cstate + iv * gv;
            float hv = ov * tanhf(cstate);
            uint32_t hvt = f2tf32(hv);
            g_hT[(t + 1) & 1][(hb + hh_e) * BB + b_e] = __uint_as_float(hvt);
            g_hs[((size_t)t * BB + b_e) * HH + hb + hh_e] = __uint_as_float(hvt);
        }

        __syncthreads();
        if (tid == 0) {
            __threadfence();
            atomicAdd(&g_done[t], 1u);
        }
    }
}

// ---------------------------------------------------------------------------
// Launch
// ---------------------------------------------------------------------------
extern "C" void kernel_launch(void* const* d_in, const int* in_sizes, int n_in,
                              void* d_out, int out_size) {
    const float* x     = (const float*)d_in[0];
    const float* W_ih  = (const float*)d_in[1];
    const float* W_hh  = (const float*)d_in[2];
    const float* b_ih  = (const float*)d_in[3];
    const float* b_hh  = (const float*)d_in[4];
    const float* W_key = (const float*)d_in[5];
    const float* b_key = (const float*)d_in[6];
    const float* W_val = (const float*)d_in[7];
    const float* b_val = (const float*)d_in[8];
    float* out = (float*)d_out;

    float* xg_ptr = nullptr;
    float* hs_ptr = nullptr;
    uint32_t *xt_ptr = nullptr, *wih_ptr = nullptr, *wkey_ptr = nullptr, *wval_ptr = nullptr;
    cudaGetSymbolAddress((void**)&xg_ptr, g_xg);
    cudaGetSymbolAddress((void**)&hs_ptr, g_hs);
    cudaGetSymbolAddress((void**)&xt_ptr, g_xt);
    cudaGetSymbolAddress((void**)&wih_ptr, g_wih);
    cudaGetSymbolAddress((void**)&wkey_ptr, g_wkey);
    cudaGetSymbolAddress((void**)&wval_ptr, g_wval);

    const int M = BB * SS;   // 32768
    const int LSTM_SMEM = (32768 + 2 * 8 * 32 * HSTRIDE) * 4;   // 212,992 B
    const int GEMM_SMEM = 3 * 2 * 128 * SA * 4;                 // 110,592 B

    cudaFuncSetAttribute(lstm_persistent,
                         cudaFuncAttributeMaxDynamicSharedMemorySize, LSTM_SMEM);
    cudaFuncSetAttribute(gemm_tf32,
                         cudaFuncAttributeMaxDynamicSharedMemorySize, GEMM_SMEM);

    // Pre-convert gemm inputs to tf32 bits (bit-identical to in-loop cvt)
    {
        int n;
        n = BB * SS * EE / 4;
        cvt_tf32_kernel<<<(n + 255) / 256, 256>>>(x, xt_ptr, n);
        n = GG * EE / 4;
        cvt_tf32_kernel<<<(n + 255) / 256, 256>>>(W_ih, wih_ptr, n);
        n = DKV * HH / 4;
        cvt_tf32_kernel<<<(n + 255) / 256, 256>>>(W_key, wkey_ptr, n);
        cvt_tf32_kernel<<<(n + 255) / 256, 256>>>(W_val, wval_ptr, n);
    }

    // Phase A: xg[S][B][4H] = perm1( x @ W_ih^T + b_ih + b_hh )
    {
        dim3 grid(GG / 128, M / 128);
        gemm_tf32<<<grid, 256, GEMM_SMEM>>>(xt_ptr, wih_ptr, b_ih, b_hh, xg_ptr, M, GG, EE, 1);
    }

    // Phase B: persistent tf32-MMA LSTM recurrence (single launch)
    lstm_persistent<<<NBLK, NTHR, LSTM_SMEM>>>(W_hh);

    // Phase C: keys / values; hs holds tf32 bits -> out rows permuted (perm=2)
    {
        dim3 grid(DKV / 128, M / 128);
        gemm_tf32<<<grid, 256, GEMM_SMEM>>>((const uint32_t*)hs_ptr, wkey_ptr, b_key, nullptr,
                                            out, M, DKV, HH, 2);
        gemm_tf32<<<grid, 256, GEMM_SMEM>>>((const uint32_t*)hs_ptr, wval_ptr, b_val, nullptr,
                                            out + (size_t)M * DKV, M, DKV, HH, 2);
    }
}